// round 13
// baseline (speedup 1.0000x reference)
#include <cuda_runtime.h>
#include <cuda_bf16.h>
#include <cstdint>

// Problem constants
#define BB 4096
#define SS 200
#define DD 64
#define HH 36
#define NROWS (BB*SS)          // 819200
#define ROWF  (SS*HH)          // 7200 floats of h per batch

// ---------------- device scratch (no allocations allowed) ----------------
// h stored TRANSPOSED per batch: g_h[b*7200 + j*200 + s]
__device__ float g_h[(size_t)NROWS * HH];     // 118 MB staged h^T
__device__ float g_part[BB * 72];             // per-batch [sum36|sq36]
__device__ float g_stats[72];                 // reduced sums

// ---------------- helpers ----------------
__device__ __forceinline__ unsigned pack2(unsigned short a, unsigned short b) {
    return (unsigned)a | ((unsigned)b << 16);
}
__device__ __forceinline__ void bfsplit(float x, unsigned short& hi, unsigned short& lo) {
    __nv_bfloat16 bh = __float2bfloat16_rn(x);
    float r = x - __bfloat162float(bh);
    __nv_bfloat16 bl = __float2bfloat16_rn(r);
    hi = __bfloat16_as_ushort(bh);
    lo = __bfloat16_as_ushort(bl);
}
// m16n8k16 row.col bf16 MMA, fp32 accum (standard PTX, sm_80+)
#define MMA16816(c, a0, a1, a2, a3, b0, b1) \
    asm volatile("mma.sync.aligned.m16n8k16.row.col.f32.bf16.bf16.f32 " \
        "{%0,%1,%2,%3}, {%4,%5,%6,%7}, {%8,%9}, {%0,%1,%2,%3};" \
        : "+f"(c[0]), "+f"(c[1]), "+f"(c[2]), "+f"(c[3]) \
        : "r"(a0), "r"(a1), "r"(a2), "r"(a3), "r"(b0), "r"(b1))

// ---------------- pass 1: HMMA split-bf16 GEMM ----------------
// A = hist [208 pad][64] bf16 hi/lo, 144B row pitch (conflict-free frag LDS).
// B = M^T as [40 pad][64] bf16 hi/lo, same pitch.
// 13 m-tiles x 5 n-tiles x 4 k-steps x 3 split passes.
#define AH_O 0
#define AL_O 29952
#define BH_O 59904
#define BL_O 65664
#define U_O  71424      // float u[40] (36 + zero pad)
#define X_O  71584      // cbuf[64] during staging; part[6*72] in epilogue
#define SMEM1 73312

__global__ void __launch_bounds__(192)
pass1_kernel(const float* __restrict__ hist,
             const float* __restrict__ cand,
             const float* __restrict__ W1,
             const float* __restrict__ b1)
{
    extern __shared__ unsigned char smem[];
    const int tid = threadIdx.x;
    const int w   = tid >> 5;
    const int l   = tid & 31;
    const int b   = blockIdx.x;
    float* u    = (float*)(smem + U_O);
    float* xbuf = (float*)(smem + X_O);      // cbuf now, part later

    if (tid < 64) xbuf[tid] = cand[b * 64 + tid];
    // zero pad rows: A rows 200-207 (288 uints each), B rows 36-39 (144 each)
    for (int i = tid; i < 288; i += 192) {
        *(unsigned*)(smem + AH_O + 28800 + 4 * i) = 0;
        *(unsigned*)(smem + AL_O + 28800 + 4 * i) = 0;
    }
    for (int i = tid; i < 144; i += 192) {
        *(unsigned*)(smem + BH_O + 5184 + 4 * i) = 0;
        *(unsigned*)(smem + BL_O + 5184 + 4 * i) = 0;
    }
    __syncthreads();

    // stage A: hist -> bf16 hi/lo, [row][k], 144B pitch
    {
        const float4* h4 = (const float4*)(hist + (size_t)b * (SS * DD));
        for (int f = tid; f < 3200; f += 192) {
            float4 v = h4[f];
            int row = f >> 4, q = f & 15;
            unsigned short h0,l0,h1,l1,h2,l2,h3,l3;
            bfsplit(v.x, h0, l0); bfsplit(v.y, h1, l1);
            bfsplit(v.z, h2, l2); bfsplit(v.w, h3, l3);
            unsigned off = (unsigned)(row * 144 + q * 8);
            *(uint2*)(smem + AH_O + off) = make_uint2(pack2(h0,h1), pack2(h2,h3));
            *(uint2*)(smem + AL_O + off) = make_uint2(pack2(l0,l1), pack2(l2,l3));
        }
    }
    // stage B: Bs[j][k] = M[k][j] = W1[64+k][j]-W1[128+k][j]+cand[k]*W1[192+k][j]
    for (int e = tid; e < 36 * 64; e += 192) {
        int j = e >> 6, k = e & 63;
        float m = W1[(64 + k) * 36 + j] - W1[(128 + k) * 36 + j]
                + xbuf[k] * W1[(192 + k) * 36 + j];
        unsigned short mh, ml;
        bfsplit(m, mh, ml);
        *(unsigned short*)(smem + BH_O + j * 144 + k * 2) = mh;
        *(unsigned short*)(smem + BL_O + j * 144 + k * 2) = ml;
    }
    if (tid >= 36 && tid < 40) u[tid] = 0.f;
    if (tid < 36) {
        float a = b1[tid];
        #pragma unroll 8
        for (int k = 0; k < 64; k++)
            a += xbuf[k] * (W1[k * 36 + tid] + W1[(128 + k) * 36 + tid]);
        u[tid] = a;
    }
    __syncthreads();

    // ---- MMA mainloop: warp w owns m-tiles {w, w+6, w+12<=12} ----
    const int g  = l >> 2;               // 0..7
    const int lp = (l & 3) * 2;          // 0,2,4,6
    const unsigned lane_off = (unsigned)(g * 144 + lp * 2);
    float ss[5][2] = {{0.f,0.f},{0.f,0.f},{0.f,0.f},{0.f,0.f},{0.f,0.f}};
    float sq[5][2] = {{0.f,0.f},{0.f,0.f},{0.f,0.f},{0.f,0.f},{0.f,0.f}};
    float* dst = g_h + (size_t)b * ROWF;

    for (int t = 0; t < 3; t++) {
        int mt = w + 6 * t;
        if (mt > 12) break;
        float acc[5][4];
        #pragma unroll
        for (int n = 0; n < 5; n++)
            #pragma unroll
            for (int c = 0; c < 4; c++) acc[n][c] = 0.f;

        #pragma unroll
        for (int ks = 0; ks < 4; ks++) {
            const unsigned char* ap = smem + mt * 2304 + ks * 32 + lane_off;
            unsigned ah0 = *(const unsigned*)(ap + AH_O);
            unsigned ah1 = *(const unsigned*)(ap + AH_O + 1152);
            unsigned ah2 = *(const unsigned*)(ap + AH_O + 16);
            unsigned ah3 = *(const unsigned*)(ap + AH_O + 1168);
            unsigned al0 = *(const unsigned*)(ap + AL_O);
            unsigned al1 = *(const unsigned*)(ap + AL_O + 1152);
            unsigned al2 = *(const unsigned*)(ap + AL_O + 16);
            unsigned al3 = *(const unsigned*)(ap + AL_O + 1168);
            #pragma unroll
            for (int n = 0; n < 5; n++) {
                const unsigned char* bp = smem + n * 1152 + ks * 32 + lane_off;
                unsigned bh0 = *(const unsigned*)(bp + BH_O);
                unsigned bh1 = *(const unsigned*)(bp + BH_O + 16);
                unsigned bl0 = *(const unsigned*)(bp + BL_O);
                unsigned bl1 = *(const unsigned*)(bp + BL_O + 16);
                MMA16816(acc[n], ah0, ah1, ah2, ah3, bh0, bh1);
                MMA16816(acc[n], ah0, ah1, ah2, ah3, bl0, bl1);
                MMA16816(acc[n], al0, al1, al2, al3, bh0, bh1);
            }
        }

        // epilogue for this m-tile: bias, store h^T, accumulate stats
        const int r0 = mt * 16 + g;
        const int r1 = r0 + 8;
        const bool rv1 = (r1 < 200);
        #pragma unroll
        for (int n = 0; n < 5; n++) {
            int j0 = n * 8 + lp, j1 = j0 + 1;
            float u0 = u[j0], u1 = u[j1];
            float h00 = acc[n][0] + u0, h01 = acc[n][1] + u1;
            float h10 = acc[n][2] + u0, h11 = acc[n][3] + u1;
            bool jv0 = (j0 < 36), jv1 = (j1 < 36);
            if (jv0) {
                dst[j0 * SS + r0] = h00;
                ss[n][0] += h00; sq[n][0] += h00 * h00;
                if (rv1) {
                    dst[j0 * SS + r1] = h10;
                    ss[n][0] += h10; sq[n][0] += h10 * h10;
                }
            }
            if (jv1) {
                dst[j1 * SS + r0] = h01;
                ss[n][1] += h01; sq[n][1] += h01 * h01;
                if (rv1) {
                    dst[j1 * SS + r1] = h11;
                    ss[n][1] += h11; sq[n][1] += h11 * h11;
                }
            }
        }
    }

    // reduce stats over the 8 lanes sharing each j (stride-4 butterfly)
    #pragma unroll
    for (int n = 0; n < 5; n++)
        #pragma unroll
        for (int p = 0; p < 2; p++) {
            float s = ss[n][p], q = sq[n][p];
            s += __shfl_xor_sync(0xffffffffu, s, 4);
            s += __shfl_xor_sync(0xffffffffu, s, 8);
            s += __shfl_xor_sync(0xffffffffu, s, 16);
            q += __shfl_xor_sync(0xffffffffu, q, 4);
            q += __shfl_xor_sync(0xffffffffu, q, 8);
            q += __shfl_xor_sync(0xffffffffu, q, 16);
            ss[n][p] = s; sq[n][p] = q;
        }
    if (l < 4) {
        #pragma unroll
        for (int n = 0; n < 5; n++)
            #pragma unroll
            for (int p = 0; p < 2; p++) {
                int j = n * 8 + l * 2 + p;
                if (j < 36) {
                    xbuf[w * 72 + j]      = ss[n][p];
                    xbuf[w * 72 + 36 + j] = sq[n][p];
                }
            }
    }
    __syncthreads();
    if (tid < 72) {
        float a = 0.f;
        #pragma unroll
        for (int gr = 0; gr < 6; gr++) a += xbuf[gr * 72 + tid];
        g_part[b * 72 + tid] = a;
    }
}

// ---------------- pass 2: reduce stat partials (deterministic) ------------
__global__ void __launch_bounds__(256)
reduce_stats_kernel()
{
    __shared__ float red[256];
    const int r   = blockIdx.x;      // 0..71
    const int tid = threadIdx.x;
    float s = 0.f;
    for (int b = tid; b < BB; b += 256) s += g_part[b * 72 + r];
    red[tid] = s;
    __syncthreads();
    #pragma unroll
    for (int o = 128; o > 0; o >>= 1) {
        if (tid < o) red[tid] += red[tid + o];
        __syncthreads();
    }
    if (tid == 0) g_stats[r] = red[0];
}

// ---------------- pass 3: BN + Dice + W2 + weighted pooling ---------------
// (R9 fused winner, byte-identical)
__global__ void __launch_bounds__(256)
pass3_kernel(const float* __restrict__ hist,
             const float* __restrict__ gamma,
             const float* __restrict__ beta,
             const float* __restrict__ alpha,
             const float* __restrict__ W2,
             const float* __restrict__ b2,
             float* __restrict__ out)
{
    __shared__ float htile[ROWF];      // 28,800 B, h^T [j][s] contiguous
    __shared__ float wrow[SS];
    __shared__ float acoef[36], ccoef[36], w2s[36];
    __shared__ float pool[256];

    const int tid = threadIdx.x;
    const int b   = blockIdx.x;

    {
        const float4* src4 = (const float4*)(g_h + (size_t)b * ROWF);
        float4* ht4 = (float4*)htile;
        for (int i = tid; i < ROWF / 4; i += 256) ht4[i] = src4[i];
    }

    if (tid < 36) {
        float sm = g_stats[tid];
        float sqv = g_stats[36 + tid];
        const float invN = 1.0f / (float)NROWS;
        float mu   = sm * invN;
        float var  = sqv * invN - mu * mu;
        float rstd = rsqrtf(var + 1e-5f);
        float a    = gamma[tid] * rstd;
        acoef[tid] = a;
        ccoef[tid] = beta[tid] - mu * a;
        w2s[tid]   = W2[tid];
    }
    const float alph = alpha[0];
    const float b2v  = b2[0];
    __syncthreads();

    if (tid < SS) {
        const int s = tid;
        float sum = 0.f, ssq = 0.f;
        #pragma unroll
        for (int j = 0; j < 36; j++) {
            float v = acoef[j] * htile[j * SS + s] + ccoef[j];
            sum += v;
            ssq += v * v;
        }
        float mean = sum * (1.0f / 36.0f);
        float var  = ssq * (1.0f / 36.0f) - mean * mean;
        float rs   = rsqrtf(var + 1e-3f);
        float wa = 0.f;
        #pragma unroll
        for (int j = 0; j < 36; j++) {
            float v  = acoef[j] * htile[j * SS + s] + ccoef[j];
            float x  = (v - mean) * rs;
            float ps = 1.0f / (1.0f + __expf(-x));
            float hv = v * (ps + (1.0f - ps) * alph);
            wa += hv * w2s[j];
        }
        wrow[s] = wa + b2v;
    }
    __syncthreads();

    const float* hb = hist + (size_t)b * (SS * DD);
    const int d = tid & 63;
    const int q = tid >> 6;            // 0..3
    float acc = 0.f;
    for (int s = q; s < SS; s += 4)
        acc += wrow[s] * hb[s * 64 + d];
    pool[tid] = acc;
    __syncthreads();
    if (tid < 64)
        out[b * 64 + tid] = pool[tid] + pool[64 + tid] + pool[128 + tid] + pool[192 + tid];
}

// ---------------- launch ----------------
extern "C" void kernel_launch(void* const* d_in, const int* in_sizes, int n_in,
                              void* d_out, int out_size)
{
    const float* history = (const float*)d_in[0];
    const float* cand    = (const float*)d_in[1];
    const float* W1      = (const float*)d_in[2];
    const float* b1      = (const float*)d_in[3];
    const float* gamma   = (const float*)d_in[4];
    const float* beta    = (const float*)d_in[5];
    const float* alpha   = (const float*)d_in[6];
    const float* W2      = (const float*)d_in[7];
    const float* b2      = (const float*)d_in[8];
    float* out = (float*)d_out;

    cudaFuncSetAttribute(pass1_kernel,
                         cudaFuncAttributeMaxDynamicSharedMemorySize, SMEM1);

    pass1_kernel<<<BB, 192, SMEM1>>>(history, cand, W1, b1);
    reduce_stats_kernel<<<72, 256>>>();
    pass3_kernel<<<BB, 256>>>(history, gamma, beta, alpha, W2, b2, out);
}

// round 15
// speedup vs baseline: 1.2086x; 1.2086x over previous
#include <cuda_runtime.h>
#include <cstdint>

// Problem constants
#define BB 4096
#define SS 200
#define DD 64
#define HH 36
#define NROWS (BB*SS)          // 819200
#define ROWF  (SS*HH)          // 7200 floats of h per batch

// ---------------- device scratch (no allocations allowed) ----------------
// h stored TRANSPOSED per batch: g_h[b*7200 + j*200 + s]
__device__ float g_h[(size_t)NROWS * HH];     // 118 MB staged h^T
__device__ float g_part[BB * 144];            // per-block per-rowgroup [sum36|sq36]
__device__ float g_stats[72];                 // reduced sums

// packed fp32x2 FMA (FFMA2) — double-rate fp32 on sm_103a
__device__ __forceinline__ void ffma2(unsigned long long& d,
                                      unsigned long long a,
                                      unsigned long long b) {
    asm("fma.rn.f32x2 %0, %1, %2, %0;" : "+l"(d) : "l"(a), "l"(b));
}
// splat one f32 into both halves of a packed f32x2
__device__ __forceinline__ unsigned long long splat2(float h) {
    unsigned long long r;
    unsigned int hu = __float_as_uint(h);
    asm("mov.b64 %0, {%1, %1};" : "=l"(r) : "r"(hu));
    return r;
}
// 4-byte async copy global->shared (LDGSTS)
__device__ __forceinline__ void cpasync4(unsigned int dst, const float* src) {
    asm volatile("cp.async.ca.shared.global [%0], [%1], 4;"
                 :: "r"(dst), "l"(src));
}
__device__ __forceinline__ void cp_commit() {
    asm volatile("cp.async.commit_group;");
}
template <int N>
__device__ __forceinline__ void cp_wait() {
    asm volatile("cp.async.wait_group %0;" :: "n"(N));
}
__device__ __forceinline__ unsigned int smem_u32(const void* p) {
    unsigned int a;
    asm("{ .reg .u64 t; cvta.to.shared.u64 t, %1; cvt.u32.u64 %0, t; }"
        : "=r"(a) : "l"(p));
    return a;
}

// ---------------- pass 1: per-batch GEMM h = hist @ M_b + u_b -------------
// (R9 winner, byte-identical: col-pair FFMA2, cp.async 4-stage pipeline, (192,4))
#define HP_PITCH  17
#define HP_BUFB   13600                 // 200*17*4 bytes per buffer
#define MS_OFF    27200
#define U_OFF     36416
#define CB_OFF    36560
#define SMEM1     36816
#define KSTAGE    16                    // k per stage
#define NSTAGE    4

__global__ void __launch_bounds__(192, 4)
pass1_kernel(const float* __restrict__ hist,
             const float* __restrict__ cand,
             const float* __restrict__ W1,
             const float* __restrict__ b1)
{
    extern __shared__ unsigned char smem_raw[];
    float* hpF  = (float*)smem_raw;
    float* msm  = (float*)(smem_raw + MS_OFF);
    float* u    = (float*)(smem_raw + U_OFF);
    float* cbuf = (float*)(smem_raw + CB_OFF);

    const int tid = threadIdx.x;
    const int b   = blockIdx.x;
    const float* hb = hist + (size_t)b * (SS * DD);
    const unsigned int hp_base = smem_u32(smem_raw);

    // kick off fills for stage 0 and 1 immediately (overlaps M/u build)
    #pragma unroll
    for (int st = 0; st < 2; st++) {
        const int k0 = st * KSTAGE;
        const unsigned int dstb = hp_base + (st & 1) * HP_BUFB;
        for (int o = tid; o < SS * KSTAGE; o += 192) {
            int row = o >> 4, c = o & 15;
            cpasync4(dstb + (unsigned)(row * HP_PITCH + c) * 4,
                     hb + row * DD + k0 + c);
        }
        cp_commit();
    }

    if (tid < 64) cbuf[tid] = cand[b * 64 + tid];
    __syncthreads();

    // M[k][j] = W1[64+k][j] - W1[128+k][j] + cand[k]*W1[192+k][j]  (unsplatted)
    for (int e = tid; e < 64 * 36; e += 192) {
        int k = e / 36;
        msm[e] = W1[2304 + e] - W1[4608 + e] + cbuf[k] * W1[6912 + e];
    }
    // u[j] = b1[j] + sum_k cand[k]*(W1[k][j] + W1[128+k][j])
    if (tid < 36) {
        int j = tid;
        float a = b1[j];
        #pragma unroll 8
        for (int k = 0; k < 64; k++)
            a += cbuf[k] * (W1[k * 36 + j] + W1[(128 + k) * 36 + j]);
        u[j] = a;
    }

    // warp tiling: w = wr*3 + wc ; wr = row-group (100 rows), wc = 12 cols
    const int w  = tid >> 5;
    const int l  = tid & 31;
    const int wc = w % 3;
    const int wr = w / 3;
    const int jc = wc * 12;
    const int rowbase = wr * 100;
    const bool act = (l < 25);
    const int r0 = (rowbase + l) * HP_PITCH;

    unsigned long long acc[4][6];
    #pragma unroll
    for (int i = 0; i < 4; i++)
        #pragma unroll
        for (int j = 0; j < 6; j++) acc[i][j] = 0ull;

    // pipelined k-stages
    for (int st = 0; st < NSTAGE; st++) {
        if (st < NSTAGE - 1) cp_wait<1>(); else cp_wait<0>();
        __syncthreads();                       // stage st data visible to all

        const float* hs = hpF + (st & 1) * (HP_BUFB / 4);
        if (act) {
            const int km0 = st * KSTAGE;
            #pragma unroll 4
            for (int k = 0; k < KSTAGE; k++) {
                unsigned long long h0 = splat2(hs[r0 + k]);
                unsigned long long h1 = splat2(hs[r0 + 25 * HP_PITCH + k]);
                unsigned long long h2 = splat2(hs[r0 + 50 * HP_PITCH + k]);
                unsigned long long h3 = splat2(hs[r0 + 75 * HP_PITCH + k]);
                const ulonglong2* mp =
                    (const ulonglong2*)(msm + (km0 + k) * 36 + jc);
                ulonglong2 mA = mp[0];
                ulonglong2 mB = mp[1];
                ulonglong2 mC = mp[2];
                unsigned long long mm[6] = {mA.x, mA.y, mB.x, mB.y, mC.x, mC.y};
                #pragma unroll
                for (int j = 0; j < 6; j++) {
                    ffma2(acc[0][j], h0, mm[j]);
                    ffma2(acc[1][j], h1, mm[j]);
                    ffma2(acc[2][j], h2, mm[j]);
                    ffma2(acc[3][j], h3, mm[j]);
                }
            }
        }
        __syncthreads();                       // everyone done reading buffer
        if (st + 2 < NSTAGE) {
            const int k0 = (st + 2) * KSTAGE;
            const unsigned int dstb = hp_base + (st & 1) * HP_BUFB;
            for (int o = tid; o < SS * KSTAGE; o += 192) {
                int row = o >> 4, c = o & 15;
                cpasync4(dstb + (unsigned)(row * HP_PITCH + c) * 4,
                         hb + row * DD + k0 + c);
            }
        }
        cp_commit();                           // uniform group count per thread
    }

    // epilogue per column-pair: bias, stats, store h^T (coalesced STG.32)
    float* dst = g_h + (size_t)b * ROWF;
    const int pbase = b * 144 + wr * 72;
    #pragma unroll
    for (int j = 0; j < 6; j++) {
        float sLo = 0.f, sHi = 0.f, qLo = 0.f, qHi = 0.f;
        if (act) {
            const float uLo = u[jc + 2 * j];
            const float uHi = u[jc + 2 * j + 1];
            #pragma unroll
            for (int i = 0; i < 4; i++) {
                float lo = __uint_as_float((unsigned)(acc[i][j] & 0xffffffffull)) + uLo;
                float hi = __uint_as_float((unsigned)(acc[i][j] >> 32)) + uHi;
                sLo += lo; qLo += lo * lo;
                sHi += hi; qHi += hi * hi;
                int row = rowbase + i * 25 + l;
                dst[(jc + 2 * j) * SS + row]     = lo;
                dst[(jc + 2 * j + 1) * SS + row] = hi;
            }
        }
        #pragma unroll
        for (int off = 16; off > 0; off >>= 1) {
            sLo += __shfl_down_sync(0xffffffffu, sLo, off);
            qLo += __shfl_down_sync(0xffffffffu, qLo, off);
            sHi += __shfl_down_sync(0xffffffffu, sHi, off);
            qHi += __shfl_down_sync(0xffffffffu, qHi, off);
        }
        if (l == 0) {
            g_part[pbase + jc + 2 * j]          = sLo;
            g_part[pbase + 36 + jc + 2 * j]     = qLo;
            g_part[pbase + jc + 2 * j + 1]      = sHi;
            g_part[pbase + 36 + jc + 2 * j + 1] = qHi;
        }
    }
}

// ---------------- pass 2: reduce stat partials (deterministic) ------------
__global__ void __launch_bounds__(256)
reduce_stats_kernel()
{
    __shared__ float red[256];
    const int r   = blockIdx.x;      // 0..71
    const int tid = threadIdx.x;
    float s = 0.f;
    for (int b = tid; b < BB; b += 256)
        s += g_part[b * 144 + r] + g_part[b * 144 + 72 + r];
    red[tid] = s;
    __syncthreads();
    #pragma unroll
    for (int o = 128; o > 0; o >>= 1) {
        if (tid < o) red[tid] += red[tid + o];
        __syncthreads();
    }
    if (tid == 0) g_stats[r] = red[0];
}

// ---------------- pass 3: BN + Dice + W2 + weighted pooling ---------------
// This round: NO smem htile. h^T [j][s] means thread s reads are already
// perfectly coalesced from global; second pass hits L1/L2 (28.8KB/CTA).
// Low smem + low regs -> high occupancy. Pooling loop: R3/R9 verbatim.
__global__ void __launch_bounds__(256)
pass3_kernel(const float* __restrict__ hist,
             const float* __restrict__ gamma,
             const float* __restrict__ beta,
             const float* __restrict__ alpha,
             const float* __restrict__ W2,
             const float* __restrict__ b2,
             float* __restrict__ out)
{
    __shared__ float wrow[SS];
    __shared__ float acoef[36], ccoef[36], w2s[36];
    __shared__ float pool[256];

    const int tid = threadIdx.x;
    const int b   = blockIdx.x;

    if (tid < 36) {
        float sm = g_stats[tid];
        float sq = g_stats[36 + tid];
        const float invN = 1.0f / (float)NROWS;
        float mu   = sm * invN;
        float var  = sq * invN - mu * mu;
        float rstd = rsqrtf(var + 1e-5f);
        float a    = gamma[tid] * rstd;
        acoef[tid] = a;
        ccoef[tid] = beta[tid] - mu * a;
        w2s[tid]   = W2[tid];
    }
    const float alph = alpha[0];
    const float b2v  = b2[0];
    __syncthreads();

    if (tid < SS) {
        const float* hT = g_h + (size_t)b * ROWF + tid;   // column s = tid
        // pass A: mean & variance of BN-transformed values (36-deep LDG MLP)
        float sum = 0.f, ssq = 0.f;
        #pragma unroll
        for (int j = 0; j < 36; j++) {
            float v = acoef[j] * __ldg(hT + j * SS) + ccoef[j];
            sum += v;
            ssq += v * v;
        }
        float mean = sum * (1.0f / 36.0f);
        float var  = ssq * (1.0f / 36.0f) - mean * mean;
        float rs   = rsqrtf(var + 1e-3f);
        // pass B: Dice + W2 dot (re-read; L1/L2 resident)
        float wa = 0.f;
        #pragma unroll
        for (int j = 0; j < 36; j++) {
            float v  = acoef[j] * __ldg(hT + j * SS) + ccoef[j];
            float x  = (v - mean) * rs;
            float ps = 1.0f / (1.0f + __expf(-x));
            float hv = v * (ps + (1.0f - ps) * alph);
            wa += hv * w2s[j];
        }
        wrow[tid] = wa + b2v;
    }
    __syncthreads();

    // weighted pooling: out[b][d] = sum_s wrow[s] * hist[b][s][d]  (R3 verbatim)
    const float* hb = hist + (size_t)b * (SS * DD);
    const int d = tid & 63;
    const int q = tid >> 6;            // 0..3
    float acc = 0.f;
    for (int s = q; s < SS; s += 4)
        acc += wrow[s] * hb[s * 64 + d];
    pool[tid] = acc;
    __syncthreads();
    if (tid < 64)
        out[b * 64 + tid] = pool[tid] + pool[64 + tid] + pool[128 + tid] + pool[192 + tid];
}

// ---------------- launch ----------------
extern "C" void kernel_launch(void* const* d_in, const int* in_sizes, int n_in,
                              void* d_out, int out_size)
{
    const float* history = (const float*)d_in[0];
    const float* cand    = (const float*)d_in[1];
    const float* W1      = (const float*)d_in[2];
    const float* b1      = (const float*)d_in[3];
    const float* gamma   = (const float*)d_in[4];
    const float* beta    = (const float*)d_in[5];
    const float* alpha   = (const float*)d_in[6];
    const float* W2      = (const float*)d_in[7];
    const float* b2      = (const float*)d_in[8];
    float* out = (float*)d_out;

    cudaFuncSetAttribute(pass1_kernel,
                         cudaFuncAttributeMaxDynamicSharedMemorySize, SMEM1);

    pass1_kernel<<<BB, 192, SMEM1>>>(history, cand, W1, b1);
    reduce_stats_kernel<<<72, 256>>>();
    pass3_kernel<<<BB, 256>>>(history, gamma, beta, alpha, W2, b2, out);
}

// round 17
// speedup vs baseline: 1.3315x; 1.1017x over previous
#include <cuda_runtime.h>
#include <cuda_fp16.h>
#include <cstdint>

// Problem constants
#define BB 4096
#define SS 200
#define DD 64
#define HH 36
#define NROWS (BB*SS)          // 819200
#define ROWF  (SS*HH)          // 7200 h values per batch

// ---------------- device scratch (no allocations allowed) ----------------
// h stored TRANSPOSED per batch in fp16: g_h[b*7200 + j*200 + s]
__device__ __half g_h[(size_t)NROWS * HH];    // 59 MB staged h^T (fp16)
__device__ float g_part[BB * 144];            // per-block per-rowgroup [sum36|sq36]
__device__ float g_stats[72];                 // reduced sums

// packed fp32x2 FMA (FFMA2) — double-rate fp32 on sm_103a
__device__ __forceinline__ void ffma2(unsigned long long& d,
                                      unsigned long long a,
                                      unsigned long long b) {
    asm("fma.rn.f32x2 %0, %1, %2, %0;" : "+l"(d) : "l"(a), "l"(b));
}
// splat one f32 into both halves of a packed f32x2
__device__ __forceinline__ unsigned long long splat2(float h) {
    unsigned long long r;
    unsigned int hu = __float_as_uint(h);
    asm("mov.b64 %0, {%1, %1};" : "=l"(r) : "r"(hu));
    return r;
}
// 4-byte async copy global->shared (LDGSTS)
__device__ __forceinline__ void cpasync4(unsigned int dst, const float* src) {
    asm volatile("cp.async.ca.shared.global [%0], [%1], 4;"
                 :: "r"(dst), "l"(src));
}
__device__ __forceinline__ void cp_commit() {
    asm volatile("cp.async.commit_group;");
}
template <int N>
__device__ __forceinline__ void cp_wait() {
    asm volatile("cp.async.wait_group %0;" :: "n"(N));
}
__device__ __forceinline__ unsigned int smem_u32(const void* p) {
    unsigned int a;
    asm("{ .reg .u64 t; cvta.to.shared.u64 t, %1; cvt.u32.u64 %0, t; }"
        : "=r"(a) : "l"(p));
    return a;
}

// ---------------- pass 1: per-batch GEMM h = hist @ M_b + u_b -------------
// (R9 winner structure; ONLY the h store is fp16)
#define HP_PITCH  17
#define HP_BUFB   13600                 // 200*17*4 bytes per buffer
#define MS_OFF    27200
#define U_OFF     36416
#define CB_OFF    36560
#define SMEM1     36816
#define KSTAGE    16                    // k per stage
#define NSTAGE    4

__global__ void __launch_bounds__(192, 4)
pass1_kernel(const float* __restrict__ hist,
             const float* __restrict__ cand,
             const float* __restrict__ W1,
             const float* __restrict__ b1)
{
    extern __shared__ unsigned char smem_raw[];
    float* hpF  = (float*)smem_raw;
    float* msm  = (float*)(smem_raw + MS_OFF);
    float* u    = (float*)(smem_raw + U_OFF);
    float* cbuf = (float*)(smem_raw + CB_OFF);

    const int tid = threadIdx.x;
    const int b   = blockIdx.x;
    const float* hb = hist + (size_t)b * (SS * DD);
    const unsigned int hp_base = smem_u32(smem_raw);

    // kick off fills for stage 0 and 1 immediately (overlaps M/u build)
    #pragma unroll
    for (int st = 0; st < 2; st++) {
        const int k0 = st * KSTAGE;
        const unsigned int dstb = hp_base + (st & 1) * HP_BUFB;
        for (int o = tid; o < SS * KSTAGE; o += 192) {
            int row = o >> 4, c = o & 15;
            cpasync4(dstb + (unsigned)(row * HP_PITCH + c) * 4,
                     hb + row * DD + k0 + c);
        }
        cp_commit();
    }

    if (tid < 64) cbuf[tid] = cand[b * 64 + tid];
    __syncthreads();

    // M[k][j] = W1[64+k][j] - W1[128+k][j] + cand[k]*W1[192+k][j]  (unsplatted)
    for (int e = tid; e < 64 * 36; e += 192) {
        int k = e / 36;
        msm[e] = W1[2304 + e] - W1[4608 + e] + cbuf[k] * W1[6912 + e];
    }
    // u[j] = b1[j] + sum_k cand[k]*(W1[k][j] + W1[128+k][j])
    if (tid < 36) {
        int j = tid;
        float a = b1[j];
        #pragma unroll 8
        for (int k = 0; k < 64; k++)
            a += cbuf[k] * (W1[k * 36 + j] + W1[(128 + k) * 36 + j]);
        u[j] = a;
    }

    // warp tiling: w = wr*3 + wc ; wr = row-group (100 rows), wc = 12 cols
    const int w  = tid >> 5;
    const int l  = tid & 31;
    const int wc = w % 3;
    const int wr = w / 3;
    const int jc = wc * 12;
    const int rowbase = wr * 100;
    const bool act = (l < 25);
    const int r0 = (rowbase + l) * HP_PITCH;

    unsigned long long acc[4][6];
    #pragma unroll
    for (int i = 0; i < 4; i++)
        #pragma unroll
        for (int j = 0; j < 6; j++) acc[i][j] = 0ull;

    // pipelined k-stages
    for (int st = 0; st < NSTAGE; st++) {
        if (st < NSTAGE - 1) cp_wait<1>(); else cp_wait<0>();
        __syncthreads();                       // stage st data visible to all

        const float* hs = hpF + (st & 1) * (HP_BUFB / 4);
        if (act) {
            const int km0 = st * KSTAGE;
            #pragma unroll 4
            for (int k = 0; k < KSTAGE; k++) {
                unsigned long long h0 = splat2(hs[r0 + k]);
                unsigned long long h1 = splat2(hs[r0 + 25 * HP_PITCH + k]);
                unsigned long long h2 = splat2(hs[r0 + 50 * HP_PITCH + k]);
                unsigned long long h3 = splat2(hs[r0 + 75 * HP_PITCH + k]);
                const ulonglong2* mp =
                    (const ulonglong2*)(msm + (km0 + k) * 36 + jc);
                ulonglong2 mA = mp[0];
                ulonglong2 mB = mp[1];
                ulonglong2 mC = mp[2];
                unsigned long long mm[6] = {mA.x, mA.y, mB.x, mB.y, mC.x, mC.y};
                #pragma unroll
                for (int j = 0; j < 6; j++) {
                    ffma2(acc[0][j], h0, mm[j]);
                    ffma2(acc[1][j], h1, mm[j]);
                    ffma2(acc[2][j], h2, mm[j]);
                    ffma2(acc[3][j], h3, mm[j]);
                }
            }
        }
        __syncthreads();                       // everyone done reading buffer
        if (st + 2 < NSTAGE) {
            const int k0 = (st + 2) * KSTAGE;
            const unsigned int dstb = hp_base + (st & 1) * HP_BUFB;
            for (int o = tid; o < SS * KSTAGE; o += 192) {
                int row = o >> 4, c = o & 15;
                cpasync4(dstb + (unsigned)(row * HP_PITCH + c) * 4,
                         hb + row * DD + k0 + c);
            }
        }
        cp_commit();                           // uniform group count per thread
    }

    // epilogue per column-pair: bias, fp32 stats, fp16 store of h^T
    __half* dst = g_h + (size_t)b * ROWF;
    const int pbase = b * 144 + wr * 72;
    #pragma unroll
    for (int j = 0; j < 6; j++) {
        float sLo = 0.f, sHi = 0.f, qLo = 0.f, qHi = 0.f;
        if (act) {
            const float uLo = u[jc + 2 * j];
            const float uHi = u[jc + 2 * j + 1];
            #pragma unroll
            for (int i = 0; i < 4; i++) {
                float lo = __uint_as_float((unsigned)(acc[i][j] & 0xffffffffull)) + uLo;
                float hi = __uint_as_float((unsigned)(acc[i][j] >> 32)) + uHi;
                sLo += lo; qLo += lo * lo;
                sHi += hi; qHi += hi * hi;
                int row = rowbase + i * 25 + l;
                dst[(jc + 2 * j) * SS + row]     = __float2half_rn(lo);
                dst[(jc + 2 * j + 1) * SS + row] = __float2half_rn(hi);
            }
        }
        #pragma unroll
        for (int off = 16; off > 0; off >>= 1) {
            sLo += __shfl_down_sync(0xffffffffu, sLo, off);
            qLo += __shfl_down_sync(0xffffffffu, qLo, off);
            sHi += __shfl_down_sync(0xffffffffu, sHi, off);
            qHi += __shfl_down_sync(0xffffffffu, qHi, off);
        }
        if (l == 0) {
            g_part[pbase + jc + 2 * j]          = sLo;
            g_part[pbase + 36 + jc + 2 * j]     = qLo;
            g_part[pbase + jc + 2 * j + 1]      = sHi;
            g_part[pbase + 36 + jc + 2 * j + 1] = qHi;
        }
    }
}

// ---------------- pass 2: reduce stat partials (deterministic) ------------
__global__ void __launch_bounds__(256)
reduce_stats_kernel()
{
    __shared__ float red[256];
    const int r   = blockIdx.x;      // 0..71
    const int tid = threadIdx.x;
    float s = 0.f;
    for (int b = tid; b < BB; b += 256)
        s += g_part[b * 144 + r] + g_part[b * 144 + 72 + r];
    red[tid] = s;
    __syncthreads();
    #pragma unroll
    for (int o = 128; o > 0; o >>= 1) {
        if (tid < o) red[tid] += red[tid + o];
        __syncthreads();
    }
    if (tid == 0) g_stats[r] = red[0];
}

// ---------------- pass 3: BN + Dice + W2 + weighted pooling ---------------
// (R15 no-smem-tile version; g_h reads are fp16)
__global__ void __launch_bounds__(256)
pass3_kernel(const float* __restrict__ hist,
             const float* __restrict__ gamma,
             const float* __restrict__ beta,
             const float* __restrict__ alpha,
             const float* __restrict__ W2,
             const float* __restrict__ b2,
             float* __restrict__ out)
{
    __shared__ float wrow[SS];
    __shared__ float acoef[36], ccoef[36], w2s[36];
    __shared__ float pool[256];

    const int tid = threadIdx.x;
    const int b   = blockIdx.x;

    if (tid < 36) {
        float sm = g_stats[tid];
        float sq = g_stats[36 + tid];
        const float invN = 1.0f / (float)NROWS;
        float mu   = sm * invN;
        float var  = sq * invN - mu * mu;
        float rstd = rsqrtf(var + 1e-5f);
        float a    = gamma[tid] * rstd;
        acoef[tid] = a;
        ccoef[tid] = beta[tid] - mu * a;
        w2s[tid]   = W2[tid];
    }
    const float alph = alpha[0];
    const float b2v  = b2[0];
    __syncthreads();

    if (tid < SS) {
        const __half* hT = g_h + (size_t)b * ROWF + tid;   // column s = tid
        // pass A: mean & variance of BN-transformed values (36-deep LDG MLP)
        float sum = 0.f, ssq = 0.f;
        #pragma unroll
        for (int j = 0; j < 36; j++) {
            float v = acoef[j] * __half2float(__ldg(hT + j * SS)) + ccoef[j];
            sum += v;
            ssq += v * v;
        }
        float mean = sum * (1.0f / 36.0f);
        float var  = ssq * (1.0f / 36.0f) - mean * mean;
        float rs   = rsqrtf(var + 1e-3f);
        // pass B: Dice + W2 dot (re-read; L1/L2 resident)
        float wa = 0.f;
        #pragma unroll
        for (int j = 0; j < 36; j++) {
            float v  = acoef[j] * __half2float(__ldg(hT + j * SS)) + ccoef[j];
            float x  = (v - mean) * rs;
            float ps = 1.0f / (1.0f + __expf(-x));
            float hv = v * (ps + (1.0f - ps) * alph);
            wa += hv * w2s[j];
        }
        wrow[tid] = wa + b2v;
    }
    __syncthreads();

    // weighted pooling: out[b][d] = sum_s wrow[s] * hist[b][s][d]  (R3 verbatim)
    const float* hb = hist + (size_t)b * (SS * DD);
    const int d = tid & 63;
    const int q = tid >> 6;            // 0..3
    float acc = 0.f;
    for (int s = q; s < SS; s += 4)
        acc += wrow[s] * hb[s * 64 + d];
    pool[tid] = acc;
    __syncthreads();
    if (tid < 64)
        out[b * 64 + tid] = pool[tid] + pool[64 + tid] + pool[128 + tid] + pool[192 + tid];
}

// ---------------- launch ----------------
extern "C" void kernel_launch(void* const* d_in, const int* in_sizes, int n_in,
                              void* d_out, int out_size)
{
    const float* history = (const float*)d_in[0];
    const float* cand    = (const float*)d_in[1];
    const float* W1      = (const float*)d_in[2];
    const float* b1      = (const float*)d_in[3];
    const float* gamma   = (const float*)d_in[4];
    const float* beta    = (const float*)d_in[5];
    const float* alpha   = (const float*)d_in[6];
    const float* W2      = (const float*)d_in[7];
    const float* b2      = (const float*)d_in[8];
    float* out = (float*)d_out;

    cudaFuncSetAttribute(pass1_kernel,
                         cudaFuncAttributeMaxDynamicSharedMemorySize, SMEM1);

    pass1_kernel<<<BB, 192, SMEM1>>>(history, cand, W1, b1);
    reduce_stats_kernel<<<72, 256>>>();
    pass3_kernel<<<BB, 256>>>(history, gamma, beta, alpha, W2, b2, out);
}